// round 8
// baseline (speedup 1.0000x reference)
#include <cuda_runtime.h>
#include <math.h>

#define NN 50000
#define EE 500000

// node-space tables
__device__ __align__(16) float4 g_q[NN * 32];
__device__ __align__(16) float4 g_k[NN * 32];
__device__ __align__(16) float4 g_v[NN * 32];
__device__ __align__(16) float4 g_z[NN * 96];      // [n][2][192] flat [n][384]
// per-dst aggregates (written once by k_edge2)
__device__ __align__(16) float4 g_aggT[NN * 32];   // [n][2][64]   sum w*enc
__device__ __align__(16) float4 g_aggM[NN * 64];   // [n][2][128]  sum w*msg
__device__ __align__(16) float4 g_aggV[NN * 32];   // [n][2][64]   sum w*v[src]
__device__ __align__(8)  float2 g_asum[NN];        // [n][2]       sum w
__device__ int g_is64;
// combined weights: cols [q(0) k(128) v(256) skip(384) z(512..895)]
__device__ __align__(16) float g_Wall[128 * 896];
__device__ __align__(16) float g_ball[896];
// counting-sort scratch
__device__ int g_cnt[NN];
__device__ int g_offA[NN];
__device__ int g_bsum[128];
__device__ int g_bpre[128];
__device__ int g_off[NN + 1];
__device__ int g_pos[NN];
__device__ int g_eid[EE];

static __device__ __forceinline__ float dot4(float4 a, float4 b) {
    return a.x * b.x + a.y * b.y + a.z * b.z + a.w * b.w;
}

// ---------------------------------------------------------------------------
__global__ void k_detect(const int* __restrict__ ei32) {
    int odd_or = 0;
    #pragma unroll
    for (int i = 1; i < 64; i += 2) odd_or |= ei32[i];
    g_is64 = (odd_or == 0) ? 1 : 0;
}

// ---------------------------------------------------------------------------
// Kp: build combined weight matrix [128][896] + bias [896].
// ---------------------------------------------------------------------------
__global__ void k_prep(const float* __restrict__ Wq, const float* __restrict__ bq,
                       const float* __restrict__ Wk, const float* __restrict__ bk,
                       const float* __restrict__ Wv, const float* __restrict__ bv,
                       const float* __restrict__ Ws, const float* __restrict__ bs,
                       const float* __restrict__ We)
{
    int u = blockIdx.x * 256 + threadIdx.x;
    if (u < 128 * 512) {
        int j = u >> 9, c = u & 511;
        const float* src = (c < 128) ? Wq : (c < 256) ? Wk : (c < 384) ? Wv : Ws;
        g_Wall[j * 896 + c] = src[j * 128 + (c & 127)];
    } else if (u < 128 * 896) {
        int v = u - 128 * 512;
        int j = v / 384, col = v % 384;
        int h = col / 192, d = col % 192;
        const float4* a = (const float4*)(Wq + j * 128 + h * 64);
        const float4* b = (const float4*)(We + d * 128 + h * 64);
        float acc = 0.f;
        #pragma unroll
        for (int c = 0; c < 16; c++) acc += dot4(a[c], b[c]);
        g_Wall[j * 896 + 512 + col] = acc;
    } else if (u < 128 * 896 + 896) {
        int c = u - 128 * 896;
        if (c < 512) {
            const float* src = (c < 128) ? bq : (c < 256) ? bk : (c < 384) ? bv : bs;
            g_ball[c] = src[c & 127];
        } else {
            int col = c - 512;
            int h = col / 192, d = col % 192;
            const float4* a = (const float4*)(bq + h * 64);
            const float4* b = (const float4*)(We + d * 128 + h * 64);
            float acc = 0.f;
            #pragma unroll
            for (int cc = 0; cc < 16; cc++) acc += dot4(a[cc], b[cc]);
            g_ball[c] = acc;
        }
    }
}

// ---------------------------------------------------------------------------
// K1: node GEMM [50000,128] @ [128,896]. Tile 128x128, 8x8 per thread,
// k-panels of 32 with x transposed into smem (all LDS are .128).
// ---------------------------------------------------------------------------
__global__ void __launch_bounds__(256, 2)
k_gemm(const float* __restrict__ x, float* __restrict__ out)
{
    __shared__ float xs[32][132];   // [k][m] transposed x panel
    __shared__ float ws[32][128];   // [k][n]
    const int t = threadIdx.x;
    const int y = blockIdx.y;
    const int col0 = y * 128;

    float* dptr; int ds; int dcol0 = 0;
    if      (y == 0) { dptr = (float*)g_q; ds = 128; }
    else if (y == 1) { dptr = (float*)g_k; ds = 128; }
    else if (y == 2) { dptr = (float*)g_v; ds = 128; }
    else if (y == 3) { dptr = out;         ds = 128; }
    else { dptr = (float*)g_z; ds = 384; dcol0 = (y - 4) * 128; }

    const int m0 = blockIdx.x * 128;
    const float4* x4 = (const float4*)x;
    const int tn = t & 15, tm = t >> 4;

    float4 acc[8][2];
    #pragma unroll
    for (int r = 0; r < 8; r++) { acc[r][0] = make_float4(0.f,0.f,0.f,0.f); acc[r][1] = acc[r][0]; }

#define FMA4(A, S, Bv) { A.x += (S)*(Bv).x; A.y += (S)*(Bv).y; A.z += (S)*(Bv).z; A.w += (S)*(Bv).w; }
    for (int k0 = 0; k0 < 128; k0 += 32) {
        #pragma unroll
        for (int i = t; i < 1024; i += 256) {
            int m = i >> 3, c4 = i & 7;
            int node = m0 + m;
            float4 v = (node < NN) ? x4[(size_t)node * 32 + (k0 >> 2) + c4]
                                   : make_float4(0.f, 0.f, 0.f, 0.f);
            int kk = c4 * 4;
            xs[kk + 0][m] = v.x; xs[kk + 1][m] = v.y;
            xs[kk + 2][m] = v.z; xs[kk + 3][m] = v.w;
        }
        #pragma unroll
        for (int i = t; i < 1024; i += 256) {
            int kk = i >> 5, c4 = i & 31;
            *(float4*)&ws[kk][c4 * 4] = *(const float4*)&g_Wall[(size_t)(k0 + kk) * 896 + col0 + c4 * 4];
        }
        __syncthreads();

        #pragma unroll
        for (int kk = 0; kk < 32; kk++) {
            float4 a0 = *(const float4*)&xs[kk][tm * 8];
            float4 a1 = *(const float4*)&xs[kk][tm * 8 + 4];
            float4 b0 = *(const float4*)&ws[kk][tn * 8];
            float4 b1 = *(const float4*)&ws[kk][tn * 8 + 4];
            FMA4(acc[0][0], a0.x, b0); FMA4(acc[0][1], a0.x, b1);
            FMA4(acc[1][0], a0.y, b0); FMA4(acc[1][1], a0.y, b1);
            FMA4(acc[2][0], a0.z, b0); FMA4(acc[2][1], a0.z, b1);
            FMA4(acc[3][0], a0.w, b0); FMA4(acc[3][1], a0.w, b1);
            FMA4(acc[4][0], a1.x, b0); FMA4(acc[4][1], a1.x, b1);
            FMA4(acc[5][0], a1.y, b0); FMA4(acc[5][1], a1.y, b1);
            FMA4(acc[6][0], a1.z, b0); FMA4(acc[6][1], a1.z, b1);
            FMA4(acc[7][0], a1.w, b0); FMA4(acc[7][1], a1.w, b1);
        }
        __syncthreads();
    }
#undef FMA4

    float4 bb0 = *(const float4*)&g_ball[col0 + tn * 8];
    float4 bb1 = *(const float4*)&g_ball[col0 + tn * 8 + 4];
    #pragma unroll
    for (int r = 0; r < 8; r++) {
        int node = m0 + tm * 8 + r;
        if (node >= NN) break;
        float4 o0 = acc[r][0]; o0.x += bb0.x; o0.y += bb0.y; o0.z += bb0.z; o0.w += bb0.w;
        float4 o1 = acc[r][1]; o1.x += bb1.x; o1.y += bb1.y; o1.z += bb1.z; o1.w += bb1.w;
        float* p = dptr + (size_t)node * ds + dcol0 + tn * 8;
        *(float4*)p = o0;
        *(float4*)(p + 4) = o1;
    }
}

// ---------------------------------------------------------------------------
// Counting sort by dst
// ---------------------------------------------------------------------------
__global__ void k_hist(const void* __restrict__ ei) {
    const int e = blockIdx.x * 256 + threadIdx.x;
    if (e >= EE) return;
    int dst = g_is64 ? (int)((const long long*)ei)[EE + e] : ((const int*)ei)[EE + e];
    atomicAdd(&g_cnt[dst], 1);
}

__global__ void k_scanA() {
    __shared__ int s[512];
    const int tid = threadIdx.x;
    const int i = blockIdx.x * 512 + tid;
    int c = (i < NN) ? g_cnt[i] : 0;
    s[tid] = c;
    __syncthreads();
    #pragma unroll
    for (int o = 1; o < 512; o <<= 1) {
        int v = (tid >= o) ? s[tid - o] : 0;
        __syncthreads();
        if (tid >= o) s[tid] += v;
        __syncthreads();
    }
    if (i < NN) g_offA[i] = s[tid] - c;
    if (tid == 511) g_bsum[blockIdx.x] = s[511];
}

__global__ void k_scanB(int nchunks) {
    if (threadIdx.x == 0) {
        int run = 0;
        for (int b = 0; b < nchunks; b++) { g_bpre[b] = run; run += g_bsum[b]; }
        g_off[NN] = EE;
    }
}

__global__ void k_scanC() {
    const int i = blockIdx.x * 512 + threadIdx.x;
    if (i < NN) {
        int v = g_offA[i] + g_bpre[blockIdx.x];
        g_off[i] = v;
        g_pos[i] = v;
    }
}

__global__ void k_scatter(const void* __restrict__ ei) {
    const int e = blockIdx.x * 256 + threadIdx.x;
    if (e >= EE) return;
    int dst = g_is64 ? (int)((const long long*)ei)[EE + e] : ((const int*)ei)[EE + e];
    int p = atomicAdd(&g_pos[dst], 1);
    g_eid[p] = e;
}

// ---------------------------------------------------------------------------
// K2: warp per dst segment, lane-batched prefetch, 2-edge interleaved inner
// loop (ILP 2: two gather sets + two shfl-butterfly chains in flight).
// ---------------------------------------------------------------------------
__global__ void __launch_bounds__(256)
k_edge2(const void* __restrict__ ei,
        const float* __restrict__ tt,
        const float* __restrict__ lu,
        const float4* __restrict__ msg4,
        const float* __restrict__ tw,
        const float* __restrict__ tb)
{
    const int w = threadIdx.x >> 5, lane = threadIdx.x & 31;
    const int dst = blockIdx.x * 8 + w;
    if (dst >= NN) return;
    const int is64 = g_is64;
    const int beg = g_off[dst], end = g_off[dst + 1];

    const int lq = lane & 15;
    const float4 tw4 = ((const float4*)tw)[lq];
    const float4 tb4 = ((const float4*)tb)[lq];
    const float4 q4 = g_q[(size_t)dst * 32 + lane];
    const size_t zb0 = (size_t)dst * 96;
    const float4 za = g_z[zb0 + lane];
    const float4 zb = g_z[zb0 + 32 + lane];
    const float4 zc = g_z[zb0 + 64 + lane];

    float4 aT = make_float4(0.f, 0.f, 0.f, 0.f), aV = aT, aM0 = aT, aM1 = aT;
    float s0 = 0.f, s1 = 0.f;

    for (int base = beg; base < end; base += 32) {
        const int cnt = min(32, end - base);
        int eidl = 0, srcl = 0; float rell = 0.f;
        if (lane < cnt) {
            eidl = g_eid[base + lane];
            long long s = is64 ? ((const long long*)ei)[eidl]
                               : (long long)((const int*)ei)[eidl];
            srcl = (int)s;
            rell = tt[eidl] - lu[s];
        }

        for (int j = 0; j < cnt; j += 2) {
            const int jb = (j + 1 < cnt) ? (j + 1) : j;
            const float mk = (j + 1 < cnt) ? 1.f : 0.f;

            const int   eA = __shfl_sync(0xffffffffu, eidl, j);
            const int   sA = __shfl_sync(0xffffffffu, srcl, j);
            const float rA = __shfl_sync(0xffffffffu, rell, j);
            const int   eB = __shfl_sync(0xffffffffu, eidl, jb);
            const int   sB = __shfl_sync(0xffffffffu, srcl, jb);
            const float rB = __shfl_sync(0xffffffffu, rell, jb);

            const size_t mbA = (size_t)eA * 32;
            const size_t mbB = (size_t)eB * 32;
            float4 k4A = g_k[(size_t)sA * 32 + lane];
            float4 k4B = g_k[(size_t)sB * 32 + lane];
            float4 v4A = g_v[(size_t)sA * 32 + lane];
            float4 v4B = g_v[(size_t)sB * 32 + lane];
            float4 m4A = msg4[mbA + lane];
            float4 m4B = msg4[mbB + lane];
            float4 xmA = msg4[mbA + ((lane < 16) ? lane + 16 : lane - 16)];
            float4 xmB = msg4[mbB + ((lane < 16) ? lane + 16 : lane - 16)];

            float4 evA, evB;
            evA.x = __cosf(rA * tw4.x + tb4.x);  evB.x = __cosf(rB * tw4.x + tb4.x);
            evA.y = __cosf(rA * tw4.y + tb4.y);  evB.y = __cosf(rB * tw4.y + tb4.y);
            evA.z = __cosf(rA * tw4.z + tb4.z);  evB.z = __cosf(rB * tw4.z + tb4.z);
            evA.w = __cosf(rA * tw4.w + tb4.w);  evB.w = __cosf(rB * tw4.w + tb4.w);

            float qkA = dot4(q4, k4A);
            float qkB = dot4(q4, k4B);
            float4 AaA = (lane < 16) ? evA : xmA;
            float4 AbA = (lane < 16) ? xmA : evA;
            float4 AaB = (lane < 16) ? evB : xmB;
            float4 AbB = (lane < 16) ? xmB : evB;
            float pbA = dot4(zb, AbA) + qkA;
            float pbB = dot4(zb, AbB) + qkB;
            float p0A = dot4(za, AaA) + ((lane < 16) ? pbA : 0.f);
            float p1A = dot4(zc, m4A) + ((lane < 16) ? 0.f : pbA);
            float p0B = dot4(za, AaB) + ((lane < 16) ? pbB : 0.f);
            float p1B = dot4(zc, m4B) + ((lane < 16) ? 0.f : pbB);
            #pragma unroll
            for (int o = 16; o >= 1; o >>= 1) {
                p0A += __shfl_xor_sync(0xffffffffu, p0A, o);
                p0B += __shfl_xor_sync(0xffffffffu, p0B, o);
                p1A += __shfl_xor_sync(0xffffffffu, p1A, o);
                p1B += __shfl_xor_sync(0xffffffffu, p1B, o);
            }

            float w0A = __expf(0.125f * p0A);
            float w1A = __expf(0.125f * p1A);
            float w0B = __expf(0.125f * p0B) * mk;
            float w1B = __expf(0.125f * p1B) * mk;

            float scA = (lane < 16) ? w0A : w1A;
            float scB = (lane < 16) ? w0B : w1B;
            aT.x += scA * evA.x + scB * evB.x;
            aT.y += scA * evA.y + scB * evB.y;
            aT.z += scA * evA.z + scB * evB.z;
            aT.w += scA * evA.w + scB * evB.w;
            aV.x += scA * v4A.x + scB * v4B.x;
            aV.y += scA * v4A.y + scB * v4B.y;
            aV.z += scA * v4A.z + scB * v4B.z;
            aV.w += scA * v4A.w + scB * v4B.w;
            aM0.x += w0A * m4A.x + w0B * m4B.x;
            aM0.y += w0A * m4A.y + w0B * m4B.y;
            aM0.z += w0A * m4A.z + w0B * m4B.z;
            aM0.w += w0A * m4A.w + w0B * m4B.w;
            aM1.x += w1A * m4A.x + w1B * m4B.x;
            aM1.y += w1A * m4A.y + w1B * m4B.y;
            aM1.z += w1A * m4A.z + w1B * m4B.z;
            aM1.w += w1A * m4A.w + w1B * m4B.w;
            s0 += w0A + w0B; s1 += w1A + w1B;
        }
    }

    g_aggT[(size_t)dst * 32 + lane] = aT;
    g_aggV[(size_t)dst * 32 + lane] = aV;
    g_aggM[(size_t)dst * 64 + lane]      = aM0;
    g_aggM[(size_t)dst * 64 + 32 + lane] = aM1;
    if (lane == 0) g_asum[dst] = make_float2(s0, s1);
}

// ---------------------------------------------------------------------------
// K3: out[n,h,c] += (aggV[n,h,c] + sum_d aggE[n,h,d]*We[d,h*64+c]) / asum[n,h]
// ---------------------------------------------------------------------------
__global__ void k_final(const float* __restrict__ We, float* __restrict__ out)
{
    extern __shared__ float smf[];
    float* WeS = smf;                // 192 x 132
    float* sA  = smf + 192 * 132;    // 4 x 392
    float* sS  = sA + 4 * 392;       // 8 asums
    const int t = threadIdx.x;       // 128

    const float4* We4 = (const float4*)We;
    for (int i = t; i < 192 * 32; i += 128) {
        int d = i >> 5, c4 = i & 31;
        ((float4*)(WeS + d * 132))[c4] = We4[i];
    }

    const int j = t, h = t >> 6;
    for (int q0 = blockIdx.x * 4; q0 < NN; q0 += gridDim.x * 4) {
        __syncthreads();
        for (int i = t; i < 4 * 96; i += 128) {
            int ni = i / 96, m = i % 96;
            int node = q0 + ni;
            int hh = m / 48, d4 = m % 48;
            float4 val = (d4 < 16) ? g_aggT[(size_t)node * 32 + hh * 16 + d4]
                                   : g_aggM[(size_t)node * 64 + hh * 32 + (d4 - 16)];
            *(float4*)&sA[ni * 392 + hh * 196 + d4 * 4] = val;
        }
        if (t < 8) sS[t] = ((const float*)g_asum)[(size_t)(q0 + (t >> 1)) * 2 + (t & 1)];
        __syncthreads();

        float acc0 = 0.f, acc1 = 0.f, acc2 = 0.f, acc3 = 0.f;
        const float* a0 = sA + 0 * 392 + h * 196;
        const float* a1 = sA + 1 * 392 + h * 196;
        const float* a2 = sA + 2 * 392 + h * 196;
        const float* a3 = sA + 3 * 392 + h * 196;
        #pragma unroll 4
        for (int d = 0; d < 192; d++) {
            float wv = WeS[d * 132 + j];
            acc0 += wv * a0[d];
            acc1 += wv * a1[d];
            acc2 += wv * a2[d];
            acc3 += wv * a3[d];
        }

        const float* gv = (const float*)g_aggV;
        size_t n0 = (size_t)q0;
        out[(n0 + 0) * 128 + j] += (gv[(n0 + 0) * 128 + j] + acc0) * (1.f / (sS[0 + h] + 1e-16f));
        out[(n0 + 1) * 128 + j] += (gv[(n0 + 1) * 128 + j] + acc1) * (1.f / (sS[2 + h] + 1e-16f));
        out[(n0 + 2) * 128 + j] += (gv[(n0 + 2) * 128 + j] + acc2) * (1.f / (sS[4 + h] + 1e-16f));
        out[(n0 + 3) * 128 + j] += (gv[(n0 + 3) * 128 + j] + acc3) * (1.f / (sS[6 + h] + 1e-16f));
    }
}

// ---------------------------------------------------------------------------
extern "C" void kernel_launch(void* const* d_in, const int* in_sizes, int n_in,
                              void* d_out, int out_size)
{
    const float* x  = (const float*)d_in[0];
    const float* lu = (const float*)d_in[1];
    const float* tt = (const float*)d_in[2];
    const float* msg = (const float*)d_in[3];
    const float* tw = (const float*)d_in[4];
    const float* tb = (const float*)d_in[5];
    const float* Wq = (const float*)d_in[6];
    const float* bq = (const float*)d_in[7];
    const float* Wk = (const float*)d_in[8];
    const float* bk = (const float*)d_in[9];
    const float* Wv = (const float*)d_in[10];
    const float* bv = (const float*)d_in[11];
    const float* We = (const float*)d_in[12];
    const float* Ws = (const float*)d_in[13];
    const float* bs = (const float*)d_in[14];
    const void* ei  = d_in[15];
    float* out = (float*)d_out;

    cudaFuncSetAttribute(k_final, cudaFuncAttributeMaxDynamicSharedMemorySize, 107680);

    void* pcnt;
    cudaGetSymbolAddress(&pcnt, g_cnt);
    cudaMemsetAsync(pcnt, 0, NN * sizeof(int));

    const int NCHUNK = (NN + 511) / 512;   // 98

    k_detect<<<1, 1>>>((const int*)ei);
    k_prep<<<452, 256>>>(Wq, bq, Wk, bk, Wv, bv, Ws, bs, We);
    k_gemm<<<dim3(391, 7, 1), 256>>>(x, out);
    k_hist<<<(EE + 255) / 256, 256>>>(ei);
    k_scanA<<<NCHUNK, 512>>>();
    k_scanB<<<1, 32>>>(NCHUNK);
    k_scanC<<<NCHUNK, 512>>>();
    k_scatter<<<(EE + 255) / 256, 256>>>(ei);
    k_edge2<<<(NN + 7) / 8, 256>>>(ei, tt, lu, (const float4*)msg, tw, tb);
    k_final<<<592, 128, 107680>>>(We, out);
}